// round 10
// baseline (speedup 1.0000x reference)
#include <cuda_runtime.h>
#include <cuda_bf16.h>
#include <math.h>
#include <string.h>

#define SEQ   512
#define BATCH 64
#define INDIM 1024
#define HDIM  1024
#define GDIM  4096   // 4*H

typedef unsigned int u32;
typedef unsigned long long u64;

// ---------------------------------------------------------------------------
// Gmem scratch (all staged operands are packed bf16 hi/lo planes, u32 granules
// = bf16x2 for k-pair (2q, 2q+1), permuted so fragments load as LDS.64)
// ---------------------------------------------------------------------------
__device__ float g_xproj[(size_t)SEQ * BATCH * GDIM];              // 512 MB

// A (inp) for xproj: per (mtile 0..255, ck 0..15 of K64): [hi 128x40][lo 128x40]
#define AB_U32 (2 * 128 * 40)            // 10240 u32
__device__ u32 g_ast[(size_t)256 * 16 * AB_U32];                   // 168 MB

// W_ih: per (ntile 0..63, ck 0..15): [hi 64x40][lo 64x40]
#define WI_U32 (2 * 64 * 40)             // 5120 u32
__device__ u32 g_wih2[(size_t)64 * 16 * WI_U32];                   // 21 MB

// W_hh: per (ct 0..127, ck 0..7 of K128): [hi 32x72][lo 32x72]
#define WH_U32 (2 * 32 * 72)             // 4608 u32
__device__ u32 g_whh2[(size_t)128 * 8 * WH_U32];                   // 19 MB

// h (parity double buffer): per (par, ck 0..7): [hi 64x72][lo 64x72]
#define HB_U32 (2 * 64 * 72)             // 9216 u32
#define HPAR   (8 * HB_U32)
__device__ u32 g_hst[2 * HPAR];

__device__ float g_c_unused;             // (cell state lives in registers)

// Grid barrier flags (monotonic across graph replays; never reset)
__device__ u32 g_flags[128];

// ---------------------------------------------------------------------------
// Helpers
// ---------------------------------------------------------------------------
// RN bf16 split of a k-pair into packed hi and lo u32 granules.
__device__ __forceinline__ void bf16_split2(float v0, float v1, u32& hi, u32& lo) {
    __nv_bfloat162 h2 = __floats2bfloat162_rn(v0, v1);
    float r0 = v0 - __low2float(h2);
    float r1 = v1 - __high2float(h2);
    __nv_bfloat162 l2 = __floats2bfloat162_rn(r0, r1);
    memcpy(&hi, &h2, 4);
    memcpy(&lo, &l2, 4);
}

__device__ __forceinline__ void mma16(float* d, u32 a0, u32 a1, u32 a2, u32 a3,
                                      u32 b0, u32 b1) {
    asm volatile(
        "mma.sync.aligned.m16n8k16.row.col.f32.bf16.bf16.f32 "
        "{%0,%1,%2,%3}, {%4,%5,%6,%7}, {%8,%9}, {%0,%1,%2,%3};"
        : "+f"(d[0]), "+f"(d[1]), "+f"(d[2]), "+f"(d[3])
        : "r"(a0), "r"(a1), "r"(a2), "r"(a3), "r"(b0), "r"(b1));
}

// granule permutation within each 8-granule (16-k) group: pairs (q, q+4) adjacent
__device__ __forceinline__ int permq(int q) {
    return (q & ~7) | ((q & 3) << 1) | ((q >> 2) & 1);
}

__device__ __forceinline__ float sigmoidf_(float x) {
    return 1.f / (1.f + expf(-x));
}

__device__ __forceinline__ u32 smem_u32(const void* p) {
    u32 a;
    asm("{ .reg .u64 t; cvta.to.shared.u64 t, %1; cvt.u32.u64 %0, t; }"
        : "=r"(a) : "l"(p));
    return a;
}

__device__ __forceinline__ void cpa16(u32 dst, const float4* src) {
    asm volatile("cp.async.cg.shared.global [%0], [%1], 16;"
                 :: "r"(dst), "l"(src));
}
#define CPA_COMMIT() asm volatile("cp.async.commit_group;" ::: "memory")
#define CPA_WAIT1()  asm volatile("cp.async.wait_group 1;" ::: "memory")
#define CPA_WAIT0()  asm volatile("cp.async.wait_group 0;" ::: "memory")

// Grid-wide barrier: per-CTA release flags + one warp polls all 128.
__device__ __forceinline__ void gbar2(u32 target) {
    __threadfence();
    __syncthreads();
    if (threadIdx.x < 32) {
        if (threadIdx.x == 0) {
            asm volatile("st.release.gpu.global.u32 [%0], %1;"
                         :: "l"(&g_flags[blockIdx.x]), "r"(target) : "memory");
        }
        const u32* f = &g_flags[threadIdx.x * 4];
        for (;;) {
            u32 v0, v1, v2, v3;
            asm volatile("ld.acquire.gpu.global.u32 %0, [%1];" : "=r"(v0) : "l"(f + 0) : "memory");
            asm volatile("ld.acquire.gpu.global.u32 %0, [%1];" : "=r"(v1) : "l"(f + 1) : "memory");
            asm volatile("ld.acquire.gpu.global.u32 %0, [%1];" : "=r"(v2) : "l"(f + 2) : "memory");
            asm volatile("ld.acquire.gpu.global.u32 %0, [%1];" : "=r"(v3) : "l"(f + 3) : "memory");
            bool ok = (v0 >= target) && (v1 >= target) && (v2 >= target) && (v3 >= target);
            if (__ballot_sync(0xffffffffu, ok) == 0xffffffffu) break;
            __nanosleep(32);
        }
    }
    __syncthreads();
}

// ---------------------------------------------------------------------------
// One-time split/permute prep
// ---------------------------------------------------------------------------
__global__ void split_a_kernel(const float* __restrict__ A) {
    int gid = blockIdx.x * 256 + threadIdx.x;        // 16.78M granules
    int m = gid >> 9, qg = gid & 511;
    float2 v = *reinterpret_cast<const float2*>(A + (size_t)m * INDIM + qg * 2);
    u32 hi, lo;
    bf16_split2(v.x, v.y, hi, lo);
    int ck = qg >> 5, pq = permq(qg & 31);
    u32* dst = g_ast + (size_t)((m >> 7) * 16 + ck) * AB_U32 + (m & 127) * 40 + pq;
    dst[0] = hi;
    dst[128 * 40] = lo;
}

__global__ void split_wih_kernel(const float* __restrict__ W) {
    int gid = blockIdx.x * 256 + threadIdx.x;        // 2.1M granules
    int n = gid >> 9, qg = gid & 511;
    float2 v = *reinterpret_cast<const float2*>(W + (size_t)n * INDIM + qg * 2);
    u32 hi, lo;
    bf16_split2(v.x, v.y, hi, lo);
    int ck = qg >> 5, pq = permq(qg & 31);
    u32* dst = g_wih2 + (size_t)((n >> 6) * 16 + ck) * WI_U32 + (n & 63) * 40 + pq;
    dst[0] = hi;
    dst[64 * 40] = lo;
}

__global__ void split_whh_kernel(const float* __restrict__ W) {
    int gid = blockIdx.x * 256 + threadIdx.x;        // 2.1M granules
    int n = gid >> 9, qg = gid & 511;                // n = gate row 0..4095
    float2 v = *reinterpret_cast<const float2*>(W + (size_t)n * HDIM + qg * 2);
    u32 hi, lo;
    bf16_split2(v.x, v.y, hi, lo);
    int gg = n >> 10, j = n & 1023;
    int ct = j >> 3, r = gg * 8 + (j & 7);
    int ck = qg >> 6, pq = permq(qg & 63);
    u32* dst = g_whh2 + (size_t)(ct * 8 + ck) * WH_U32 + r * 72 + pq;
    dst[0] = hi;
    dst[32 * 72] = lo;
}

__global__ void init_state_kernel(const float* __restrict__ h0) {
    int gid = blockIdx.x * 256 + threadIdx.x;        // 32768 granules
    int b = gid >> 9, qg = gid & 511;
    float2 v = *reinterpret_cast<const float2*>(h0 + (size_t)b * HDIM + qg * 2);
    u32 hi, lo;
    bf16_split2(v.x, v.y, hi, lo);
    int ck = qg >> 6, pq = permq(qg & 63);
    u32* dst = g_hst + (size_t)ck * HB_U32 + b * 72 + pq;
    dst[0] = hi;
    dst[64 * 72] = lo;
}

// ---------------------------------------------------------------------------
// Kernel 1: x_proj = A @ W_ih^T + bias  [bf16x3 HMMA]
// Tile M=128, N=64, Kchunk=64 (16 chunks); 256 threads.
// buf (u32): Ahi 0 (128x40), Alo 5120, Whi 10240 (64x40), Wlo 12800. = 15360
// ---------------------------------------------------------------------------
#define XBUF 15360
#define XSMEM (2 * XBUF * 4)             // 122880 B

__global__ __launch_bounds__(256) void xproj_tc_kernel(
    const float* __restrict__ b1, const float* __restrict__ b2)
{
    extern __shared__ u32 smu[];
    const u32 sbase = smem_u32(smu);
    const int tid = threadIdx.x;
    const int w = tid >> 5, lane = tid & 31;
    const int g = lane >> 2, t = lane & 3;
    const int rm = w >> 1, rn = w & 1;
    const int ntile = blockIdx.x, mtile = blockIdx.y;

    const float4* asrc = reinterpret_cast<const float4*>(
        g_ast + (size_t)(mtile * 16) * AB_U32);
    const float4* wsrc = reinterpret_cast<const float4*>(
        g_wih2 + (size_t)(ntile * 16) * WI_U32);

    auto stage = [&](int ck, int buf) {
        u32 d = sbase + (u32)buf * (XBUF * 4);
        const float4* a = asrc + (size_t)ck * (AB_U32 / 4);
        const float4* ww = wsrc + (size_t)ck * (WI_U32 / 4);
        for (int i = tid; i < AB_U32 / 4; i += 256) cpa16(d + i * 16, a + i);
        for (int i = tid; i < WI_U32 / 4; i += 256)
            cpa16(d + AB_U32 * 4 + i * 16, ww + i);
    };

    float acc[2][4][4];
#pragma unroll
    for (int mt = 0; mt < 2; mt++)
#pragma unroll
        for (int nt = 0; nt < 4; nt++)
#pragma unroll
            for (int e = 0; e < 4; e++) acc[mt][nt][e] = 0.f;

    stage(0, 0);
    CPA_COMMIT();

    for (int ck = 0; ck < 16; ck++) {
        if (ck < 15) { stage(ck + 1, (ck + 1) & 1); CPA_COMMIT(); CPA_WAIT1(); }
        else CPA_WAIT0();
        __syncthreads();

        const u32* B0 = smu + (ck & 1) * XBUF;

#pragma unroll
        for (int ks = 0; ks < 4; ks++) {
            int ko = ks * 8 + 2 * t;
            uint2 axh[2], ayh[2], axl[2], ayl[2];
#pragma unroll
            for (int mt = 0; mt < 2; mt++) {
                int ar = rm * 32 + mt * 16 + g;
                axh[mt] = *reinterpret_cast<const uint2*>(&B0[ar * 40 + ko]);
                ayh[mt] = *reinterpret_cast<const uint2*>(&B0[(ar + 8) * 40 + ko]);
                axl[mt] = *reinterpret_cast<const uint2*>(&B0[5120 + ar * 40 + ko]);
                ayl[mt] = *reinterpret_cast<const uint2*>(&B0[5120 + (ar + 8) * 40 + ko]);
            }
#pragma unroll
            for (int nt = 0; nt < 4; nt++) {
                int nr = rn * 32 + nt * 8 + g;
                uint2 bh = *reinterpret_cast<const uint2*>(&B0[10240 + nr * 40 + ko]);
                uint2 bl = *reinterpret_cast<const uint2*>(&B0[12800 + nr * 40 + ko]);
#pragma unroll
                for (int mt = 0; mt < 2; mt++) {
                    float* d = acc[mt][nt];
                    mma16(d, axh[mt].x, ayh[mt].x, axh[mt].y, ayh[mt].y, bh.x, bh.y);
                    mma16(d, axl[mt].x, ayl[mt].x, axl[mt].y, ayl[mt].y, bh.x, bh.y);
                    mma16(d, axh[mt].x, ayh[mt].x, axh[mt].y, ayh[mt].y, bl.x, bl.y);
                }
            }
        }
        __syncthreads();
    }

    const int m0 = mtile * 128, n0 = ntile * 64;
#pragma unroll
    for (int mt = 0; mt < 2; mt++) {
        int row = m0 + rm * 32 + mt * 16 + g;
#pragma unroll
        for (int nt = 0; nt < 4; nt++) {
            int col = n0 + rn * 32 + nt * 8 + 2 * t;
            float bv0 = b1[col] + b2[col];
            float bv1 = b1[col + 1] + b2[col + 1];
            float2 v0 = make_float2(acc[mt][nt][0] + bv0, acc[mt][nt][1] + bv1);
            float2 v1 = make_float2(acc[mt][nt][2] + bv0, acc[mt][nt][3] + bv1);
            *reinterpret_cast<float2*>(g_xproj + (size_t)row * GDIM + col) = v0;
            *reinterpret_cast<float2*>(g_xproj + (size_t)(row + 8) * GDIM + col) = v1;
        }
    }
}

// ---------------------------------------------------------------------------
// Kernel 2: persistent LSTM recurrence [bf16x3 HMMA]. 128 CTAs x 256 threads.
// CTA ct owns 8 hidden cols -> 32 gate cols; M=64, N=32, K=1024, Kchunk=128.
// buf (u32): Hhi 0 (64x72), Hlo 4608, Whi 9216 (32x72), Wlo 11520. = 13824
// ---------------------------------------------------------------------------
#define SBUF 13824
#define SSMEM (2 * SBUF * 4)             // 110592 B

__global__ __launch_bounds__(256) void lstm_persistent(
    float* __restrict__ out, const float* __restrict__ c0, int write_tail)
{
    extern __shared__ u32 smu[];
    const u32 sbase = smem_u32(smu);
    const int tid = threadIdx.x;
    const int w = tid >> 5, lane = tid & 31;
    const int g = lane >> 2, t = lane & 3;
    const int mt = w & 3, nh = w >> 2;
    const int ct = blockIdx.x, jt = ct * 8;

    const float4* wsrc = reinterpret_cast<const float4*>(
        g_whh2 + (size_t)(ct * 8) * WH_U32);

    // cell state in registers
    float creg[2];
#pragma unroll
    for (int l = 0; l < 2; l++) {
        int pid = tid + l * 256;
        creg[l] = c0[(pid >> 3) * HDIM + jt + (pid & 7)];
    }

    __shared__ u32 s_base;
    if (tid == 0) {
        u32 b;
        asm volatile("ld.acquire.gpu.global.u32 %0, [%1];"
                     : "=r"(b) : "l"(&g_flags[blockIdx.x]) : "memory");
        s_base = b;
    }
    __syncthreads();
    const u32 base_epoch = s_base;

    auto stage = [&](const float4* hsrc, int ck, int buf) {
        u32 d = sbase + (u32)buf * (SBUF * 4);
        const float4* h = hsrc + (size_t)ck * (HB_U32 / 4);
        const float4* ww = wsrc + (size_t)ck * (WH_U32 / 4);
        for (int i = tid; i < HB_U32 / 4; i += 256) cpa16(d + i * 16, h + i);
        for (int i = tid; i < WH_U32 / 4; i += 256)
            cpa16(d + HB_U32 * 4 + i * 16, ww + i);
    };

    for (int step = 0; step < SEQ; step++) {
        const int rp = step & 1;
        const float4* hsrc = reinterpret_cast<const float4*>(
            g_hst + (size_t)rp * HPAR);
        u32* hdst = g_hst + (size_t)(rp ^ 1) * HPAR;

        // prefetch this step's xproj slice
        float2 xp[2][2];
#pragma unroll
        for (int nt = 0; nt < 2; nt++) {
            int c0i = nh * 16 + nt * 8 + 2 * t;
            int gc = (c0i >> 3) * HDIM + jt + (c0i & 7);
            int b0 = mt * 16 + g;
            xp[nt][0] = *reinterpret_cast<const float2*>(
                g_xproj + ((size_t)b0 * SEQ + step) * GDIM + gc);
            xp[nt][1] = *reinterpret_cast<const float2*>(
                g_xproj + ((size_t)(b0 + 8) * SEQ + step) * GDIM + gc);
        }

        stage(hsrc, 0, 0);
        CPA_COMMIT();

        float acc[2][4];
#pragma unroll
        for (int nt = 0; nt < 2; nt++)
#pragma unroll
            for (int e = 0; e < 4; e++) acc[nt][e] = 0.f;

        for (int ck = 0; ck < 8; ck++) {
            if (ck < 7) { stage(hsrc, ck + 1, (ck + 1) & 1); CPA_COMMIT(); CPA_WAIT1(); }
            else CPA_WAIT0();
            __syncthreads();

            const u32* B0 = smu + (ck & 1) * SBUF;
            int ar = mt * 16 + g;
#pragma unroll
            for (int ks = 0; ks < 8; ks++) {
                int ko = ks * 8 + 2 * t;
                uint2 axh = *reinterpret_cast<const uint2*>(&B0[ar * 72 + ko]);
                uint2 ayh = *reinterpret_cast<const uint2*>(&B0[(ar + 8) * 72 + ko]);
                uint2 axl = *reinterpret_cast<const uint2*>(&B0[4608 + ar * 72 + ko]);
                uint2 ayl = *reinterpret_cast<const uint2*>(&B0[4608 + (ar + 8) * 72 + ko]);
#pragma unroll
                for (int nt = 0; nt < 2; nt++) {
                    int nr = nh * 16 + nt * 8 + g;
                    uint2 bh = *reinterpret_cast<const uint2*>(&B0[9216 + nr * 72 + ko]);
                    uint2 bl = *reinterpret_cast<const uint2*>(&B0[11520 + nr * 72 + ko]);
                    float* d = acc[nt];
                    mma16(d, axh.x, ayh.x, axh.y, ayh.y, bh.x, bh.y);
                    mma16(d, axl.x, ayl.x, axl.y, ayl.y, bh.x, bh.y);
                    mma16(d, axh.x, ayh.x, axh.y, ayh.y, bl.x, bl.y);
                }
            }
            __syncthreads();
        }

        // gate exchange (overlays buf0; 64x33 floats)
        float* gsm = reinterpret_cast<float*>(smu);
#pragma unroll
        for (int nt = 0; nt < 2; nt++) {
            int c0i = nh * 16 + nt * 8 + 2 * t;
            int b0 = mt * 16 + g;
            gsm[b0 * 33 + c0i]           = acc[nt][0] + xp[nt][0].x;
            gsm[b0 * 33 + c0i + 1]       = acc[nt][1] + xp[nt][0].y;
            gsm[(b0 + 8) * 33 + c0i]     = acc[nt][2] + xp[nt][1].x;
            gsm[(b0 + 8) * 33 + c0i + 1] = acc[nt][3] + xp[nt][1].y;
        }
        __syncthreads();

        // pointwise update + write next-step h stage (bf16 hi/lo planes)
#pragma unroll
        for (int l = 0; l < 2; l++) {
            int pid = tid + l * 256;
            int b = pid >> 3, jj = pid & 7, j = jt + jj;
            float ig = gsm[b * 33 + jj];
            float fg = gsm[b * 33 + 8 + jj];
            float gg = gsm[b * 33 + 16 + jj];
            float og = gsm[b * 33 + 24 + jj];
            float cn = sigmoidf_(fg) * creg[l] + sigmoidf_(ig) * tanhf(gg);
            float h = sigmoidf_(og) * tanhf(cn);
            creg[l] = cn;
            out[(size_t)b * SEQ * HDIM + (size_t)step * HDIM + j] = h;

            __nv_bfloat16 hb = __float2bfloat16(h);
            float rl = h - __bfloat162float(hb);
            __nv_bfloat16 lb = __float2bfloat16(rl);
            int ck = j >> 7, pq = permq((j & 127) >> 1);
            u32* blk = hdst + (size_t)ck * HB_U32;
            unsigned short* hp = reinterpret_cast<unsigned short*>(blk + b * 72 + pq);
            unsigned short* lp = reinterpret_cast<unsigned short*>(blk + 64 * 72 + b * 72 + pq);
            hp[j & 1] = __bfloat16_as_ushort(hb);
            lp[j & 1] = __bfloat16_as_ushort(lb);

            if (write_tail && step == SEQ - 1) {
                float* tail = out + (size_t)SEQ * BATCH * HDIM;
                tail[b * HDIM + j] = h;
                tail[BATCH * HDIM + b * HDIM + j] = cn;
            }
        }

        if (step < SEQ - 1) gbar2(base_epoch + step + 1);
    }
}

// ---------------------------------------------------------------------------
// Launch
// ---------------------------------------------------------------------------
extern "C" void kernel_launch(void* const* d_in, const int* in_sizes, int n_in,
                              void* d_out, int out_size) {
    const float* inp  = (const float*)d_in[0];
    const float* h0   = (const float*)d_in[1];
    const float* c0   = (const float*)d_in[2];
    const float* W_ih = (const float*)d_in[3];
    const float* W_hh = (const float*)d_in[4];
    const float* b_ih = (const float*)d_in[5];
    const float* b_hh = (const float*)d_in[6];
    float* out = (float*)d_out;

    cudaFuncSetAttribute(xproj_tc_kernel,
                         cudaFuncAttributeMaxDynamicSharedMemorySize, XSMEM);
    cudaFuncSetAttribute(lstm_persistent,
                         cudaFuncAttributeMaxDynamicSharedMemorySize, SSMEM);

    split_a_kernel<<<SEQ * BATCH * INDIM / 512, 256>>>(inp);
    split_wih_kernel<<<GDIM * INDIM / 512, 256>>>(W_ih);
    split_whh_kernel<<<GDIM * HDIM / 512, 256>>>(W_hh);
    init_state_kernel<<<BATCH * HDIM / 512, 256>>>(h0);

    dim3 gx(GDIM / 64, (SEQ * BATCH) / 128);
    xproj_tc_kernel<<<gx, 256, XSMEM>>>(b_ih, b_hh);

    int tail = (out_size >= SEQ * BATCH * HDIM + 2 * BATCH * HDIM) ? 1 : 0;
    lstm_persistent<<<128, 256, SSMEM>>>(out, c0, tail);
}

// round 11
// speedup vs baseline: 1.0662x; 1.0662x over previous
#include <cuda_runtime.h>
#include <cuda_bf16.h>
#include <math.h>
#include <string.h>

#define SEQ   512
#define BATCH 64
#define INDIM 1024
#define HDIM  1024
#define GDIM  4096   // 4*H

typedef unsigned int u32;
typedef unsigned long long u64;

// ---------------------------------------------------------------------------
// Gmem scratch (all staged operands are packed bf16 hi/lo planes, u32 granules
// = bf16x2 for k-pair (2q, 2q+1), permuted so fragments load as LDS.64)
// ---------------------------------------------------------------------------
__device__ float g_xproj[(size_t)SEQ * BATCH * GDIM];              // 512 MB

// A (inp) for xproj: per (mtile 0..255, ck 0..15 of K64): [hi 128x40][lo 128x40]
#define AB_U32 (2 * 128 * 40)            // 10240 u32
__device__ u32 g_ast[(size_t)256 * 16 * AB_U32];                   // 168 MB

// W_ih: per (ntile 0..63, ck 0..15): [hi 64x40][lo 64x40]
#define WI_U32 (2 * 64 * 40)             // 5120 u32
__device__ u32 g_wih2[(size_t)64 * 16 * WI_U32];                   // 21 MB

// W_hh: per (ct 0..127, ck 0..7 of K128): [hi 32x72][lo 32x72]
#define WH_U32 (2 * 32 * 72)             // 4608 u32
__device__ u32 g_whh2[(size_t)128 * 8 * WH_U32];                   // 19 MB

// h (parity double buffer): per (par, ck 0..7): [hi 64x72][lo 64x72]
#define HB_U32 (2 * 64 * 72)             // 9216 u32
#define HPAR   (8 * HB_U32)
__device__ u32 g_hst[2 * HPAR];

__device__ float g_c_unused;             // (cell state lives in registers)

// Grid barrier flags (monotonic across graph replays; never reset)
__device__ u32 g_flags[128];

// ---------------------------------------------------------------------------
// Helpers
// ---------------------------------------------------------------------------
// RN bf16 split of a k-pair into packed hi and lo u32 granules.
__device__ __forceinline__ void bf16_split2(float v0, float v1, u32& hi, u32& lo) {
    __nv_bfloat162 h2 = __floats2bfloat162_rn(v0, v1);
    float r0 = v0 - __low2float(h2);
    float r1 = v1 - __high2float(h2);
    __nv_bfloat162 l2 = __floats2bfloat162_rn(r0, r1);
    memcpy(&hi, &h2, 4);
    memcpy(&lo, &l2, 4);
}

__device__ __forceinline__ void mma16(float* d, u32 a0, u32 a1, u32 a2, u32 a3,
                                      u32 b0, u32 b1) {
    asm volatile(
        "mma.sync.aligned.m16n8k16.row.col.f32.bf16.bf16.f32 "
        "{%0,%1,%2,%3}, {%4,%5,%6,%7}, {%8,%9}, {%0,%1,%2,%3};"
        : "+f"(d[0]), "+f"(d[1]), "+f"(d[2]), "+f"(d[3])
        : "r"(a0), "r"(a1), "r"(a2), "r"(a3), "r"(b0), "r"(b1));
}

// granule permutation within each 8-granule (16-k) group: pairs (q, q+4) adjacent
__device__ __forceinline__ int permq(int q) {
    return (q & ~7) | ((q & 3) << 1) | ((q >> 2) & 1);
}

__device__ __forceinline__ float sigmoidf_(float x) {
    return 1.f / (1.f + expf(-x));
}

__device__ __forceinline__ u32 smem_u32(const void* p) {
    u32 a;
    asm("{ .reg .u64 t; cvta.to.shared.u64 t, %1; cvt.u32.u64 %0, t; }"
        : "=r"(a) : "l"(p));
    return a;
}

__device__ __forceinline__ void cpa16(u32 dst, const float4* src) {
    asm volatile("cp.async.cg.shared.global [%0], [%1], 16;"
                 :: "r"(dst), "l"(src));
}
#define CPA_COMMIT() asm volatile("cp.async.commit_group;" ::: "memory")
#define CPA_WAIT1()  asm volatile("cp.async.wait_group 1;" ::: "memory")
#define CPA_WAIT0()  asm volatile("cp.async.wait_group 0;" ::: "memory")

// Grid-wide barrier: per-CTA release flags + one warp polls all 128.
__device__ __forceinline__ void gbar2(u32 target) {
    __threadfence();
    __syncthreads();
    if (threadIdx.x < 32) {
        if (threadIdx.x == 0) {
            asm volatile("st.release.gpu.global.u32 [%0], %1;"
                         :: "l"(&g_flags[blockIdx.x]), "r"(target) : "memory");
        }
        const u32* f = &g_flags[threadIdx.x * 4];
        for (;;) {
            u32 v0, v1, v2, v3;
            asm volatile("ld.acquire.gpu.global.u32 %0, [%1];" : "=r"(v0) : "l"(f + 0) : "memory");
            asm volatile("ld.acquire.gpu.global.u32 %0, [%1];" : "=r"(v1) : "l"(f + 1) : "memory");
            asm volatile("ld.acquire.gpu.global.u32 %0, [%1];" : "=r"(v2) : "l"(f + 2) : "memory");
            asm volatile("ld.acquire.gpu.global.u32 %0, [%1];" : "=r"(v3) : "l"(f + 3) : "memory");
            bool ok = (v0 >= target) && (v1 >= target) && (v2 >= target) && (v3 >= target);
            if (__ballot_sync(0xffffffffu, ok) == 0xffffffffu) break;
            __nanosleep(32);
        }
    }
    __syncthreads();
}

// ---------------------------------------------------------------------------
// One-time split/permute prep
// ---------------------------------------------------------------------------
__global__ void split_a_kernel(const float* __restrict__ A) {
    int gid = blockIdx.x * 256 + threadIdx.x;        // 16.78M granules
    int m = gid >> 9, qg = gid & 511;
    float2 v = *reinterpret_cast<const float2*>(A + (size_t)m * INDIM + qg * 2);
    u32 hi, lo;
    bf16_split2(v.x, v.y, hi, lo);
    int ck = qg >> 5, pq = permq(qg & 31);
    u32* dst = g_ast + (size_t)((m >> 7) * 16 + ck) * AB_U32 + (m & 127) * 40 + pq;
    dst[0] = hi;
    dst[128 * 40] = lo;
}

__global__ void split_wih_kernel(const float* __restrict__ W) {
    int gid = blockIdx.x * 256 + threadIdx.x;        // 2.1M granules
    int n = gid >> 9, qg = gid & 511;
    float2 v = *reinterpret_cast<const float2*>(W + (size_t)n * INDIM + qg * 2);
    u32 hi, lo;
    bf16_split2(v.x, v.y, hi, lo);
    int ck = qg >> 5, pq = permq(qg & 31);
    u32* dst = g_wih2 + (size_t)((n >> 6) * 16 + ck) * WI_U32 + (n & 63) * 40 + pq;
    dst[0] = hi;
    dst[64 * 40] = lo;
}

__global__ void split_whh_kernel(const float* __restrict__ W) {
    int gid = blockIdx.x * 256 + threadIdx.x;        // 2.1M granules
    int n = gid >> 9, qg = gid & 511;                // n = gate row 0..4095
    float2 v = *reinterpret_cast<const float2*>(W + (size_t)n * HDIM + qg * 2);
    u32 hi, lo;
    bf16_split2(v.x, v.y, hi, lo);
    int gg = n >> 10, j = n & 1023;
    int ct = j >> 3, r = gg * 8 + (j & 7);
    int ck = qg >> 6, pq = permq(qg & 63);
    u32* dst = g_whh2 + (size_t)(ct * 8 + ck) * WH_U32 + r * 72 + pq;
    dst[0] = hi;
    dst[32 * 72] = lo;
}

__global__ void init_state_kernel(const float* __restrict__ h0) {
    int gid = blockIdx.x * 256 + threadIdx.x;        // 32768 granules
    int b = gid >> 9, qg = gid & 511;
    float2 v = *reinterpret_cast<const float2*>(h0 + (size_t)b * HDIM + qg * 2);
    u32 hi, lo;
    bf16_split2(v.x, v.y, hi, lo);
    int ck = qg >> 6, pq = permq(qg & 63);
    u32* dst = g_hst + (size_t)ck * HB_U32 + b * 72 + pq;
    dst[0] = hi;
    dst[64 * 72] = lo;
}

// ---------------------------------------------------------------------------
// Kernel 1: x_proj = A @ W_ih^T + bias  [bf16x3 HMMA]
// Tile M=128, N=64, Kchunk=64 (16 chunks); 256 threads.
// buf (u32): Ahi 0 (128x40), Alo 5120, Whi 10240 (64x40), Wlo 12800. = 15360
// ---------------------------------------------------------------------------
#define XBUF 15360
#define XSMEM (2 * XBUF * 4)             // 122880 B

__global__ __launch_bounds__(256) void xproj_tc_kernel(
    const float* __restrict__ b1, const float* __restrict__ b2)
{
    extern __shared__ u32 smu[];
    const u32 sbase = smem_u32(smu);
    const int tid = threadIdx.x;
    const int w = tid >> 5, lane = tid & 31;
    const int g = lane >> 2, t = lane & 3;
    const int rm = w >> 1, rn = w & 1;
    const int ntile = blockIdx.x, mtile = blockIdx.y;

    const float4* asrc = reinterpret_cast<const float4*>(
        g_ast + (size_t)(mtile * 16) * AB_U32);
    const float4* wsrc = reinterpret_cast<const float4*>(
        g_wih2 + (size_t)(ntile * 16) * WI_U32);

    auto stage = [&](int ck, int buf) {
        u32 d = sbase + (u32)buf * (XBUF * 4);
        const float4* a = asrc + (size_t)ck * (AB_U32 / 4);
        const float4* ww = wsrc + (size_t)ck * (WI_U32 / 4);
        for (int i = tid; i < AB_U32 / 4; i += 256) cpa16(d + i * 16, a + i);
        for (int i = tid; i < WI_U32 / 4; i += 256)
            cpa16(d + AB_U32 * 4 + i * 16, ww + i);
    };

    float acc[2][4][4];
#pragma unroll
    for (int mt = 0; mt < 2; mt++)
#pragma unroll
        for (int nt = 0; nt < 4; nt++)
#pragma unroll
            for (int e = 0; e < 4; e++) acc[mt][nt][e] = 0.f;

    stage(0, 0);
    CPA_COMMIT();

    for (int ck = 0; ck < 16; ck++) {
        if (ck < 15) { stage(ck + 1, (ck + 1) & 1); CPA_COMMIT(); CPA_WAIT1(); }
        else CPA_WAIT0();
        __syncthreads();

        const u32* B0 = smu + (ck & 1) * XBUF;

#pragma unroll
        for (int ks = 0; ks < 4; ks++) {
            int ko = ks * 8 + 2 * t;
            uint2 axh[2], ayh[2], axl[2], ayl[2];
#pragma unroll
            for (int mt = 0; mt < 2; mt++) {
                int ar = rm * 32 + mt * 16 + g;
                axh[mt] = *reinterpret_cast<const uint2*>(&B0[ar * 40 + ko]);
                ayh[mt] = *reinterpret_cast<const uint2*>(&B0[(ar + 8) * 40 + ko]);
                axl[mt] = *reinterpret_cast<const uint2*>(&B0[5120 + ar * 40 + ko]);
                ayl[mt] = *reinterpret_cast<const uint2*>(&B0[5120 + (ar + 8) * 40 + ko]);
            }
#pragma unroll
            for (int nt = 0; nt < 4; nt++) {
                int nr = rn * 32 + nt * 8 + g;
                uint2 bh = *reinterpret_cast<const uint2*>(&B0[10240 + nr * 40 + ko]);
                uint2 bl = *reinterpret_cast<const uint2*>(&B0[12800 + nr * 40 + ko]);
#pragma unroll
                for (int mt = 0; mt < 2; mt++) {
                    float* d = acc[mt][nt];
                    mma16(d, axh[mt].x, ayh[mt].x, axh[mt].y, ayh[mt].y, bh.x, bh.y);
                    mma16(d, axl[mt].x, ayl[mt].x, axl[mt].y, ayl[mt].y, bh.x, bh.y);
                    mma16(d, axh[mt].x, ayh[mt].x, axh[mt].y, ayh[mt].y, bl.x, bl.y);
                }
            }
        }
        __syncthreads();
    }

    const int m0 = mtile * 128, n0 = ntile * 64;
#pragma unroll
    for (int mt = 0; mt < 2; mt++) {
        int row = m0 + rm * 32 + mt * 16 + g;
#pragma unroll
        for (int nt = 0; nt < 4; nt++) {
            int col = n0 + rn * 32 + nt * 8 + 2 * t;
            float bv0 = b1[col] + b2[col];
            float bv1 = b1[col + 1] + b2[col + 1];
            float2 v0 = make_float2(acc[mt][nt][0] + bv0, acc[mt][nt][1] + bv1);
            float2 v1 = make_float2(acc[mt][nt][2] + bv0, acc[mt][nt][3] + bv1);
            *reinterpret_cast<float2*>(g_xproj + (size_t)row * GDIM + col) = v0;
            *reinterpret_cast<float2*>(g_xproj + (size_t)(row + 8) * GDIM + col) = v1;
        }
    }
}

// ---------------------------------------------------------------------------
// Kernel 2: persistent LSTM recurrence [bf16x3 HMMA]. 128 CTAs x 256 threads.
// CTA ct owns 8 hidden cols -> 32 gate cols; M=64, N=32, K=1024, Kchunk=128.
// buf (u32): Hhi 0 (64x72), Hlo 4608, Whi 9216 (32x72), Wlo 11520. = 13824
// ---------------------------------------------------------------------------
#define SBUF 13824
#define SSMEM (2 * SBUF * 4)             // 110592 B

__global__ __launch_bounds__(256) void lstm_persistent(
    float* __restrict__ out, const float* __restrict__ c0, int write_tail)
{
    extern __shared__ u32 smu[];
    const u32 sbase = smem_u32(smu);
    const int tid = threadIdx.x;
    const int w = tid >> 5, lane = tid & 31;
    const int g = lane >> 2, t = lane & 3;
    const int mt = w & 3, nh = w >> 2;
    const int ct = blockIdx.x, jt = ct * 8;

    const float4* wsrc = reinterpret_cast<const float4*>(
        g_whh2 + (size_t)(ct * 8) * WH_U32);

    // cell state in registers
    float creg[2];
#pragma unroll
    for (int l = 0; l < 2; l++) {
        int pid = tid + l * 256;
        creg[l] = c0[(pid >> 3) * HDIM + jt + (pid & 7)];
    }

    __shared__ u32 s_base;
    if (tid == 0) {
        u32 b;
        asm volatile("ld.acquire.gpu.global.u32 %0, [%1];"
                     : "=r"(b) : "l"(&g_flags[blockIdx.x]) : "memory");
        s_base = b;
    }
    __syncthreads();
    const u32 base_epoch = s_base;

    auto stage = [&](const float4* hsrc, int ck, int buf) {
        u32 d = sbase + (u32)buf * (SBUF * 4);
        const float4* h = hsrc + (size_t)ck * (HB_U32 / 4);
        const float4* ww = wsrc + (size_t)ck * (WH_U32 / 4);
        for (int i = tid; i < HB_U32 / 4; i += 256) cpa16(d + i * 16, h + i);
        for (int i = tid; i < WH_U32 / 4; i += 256)
            cpa16(d + HB_U32 * 4 + i * 16, ww + i);
    };

    for (int step = 0; step < SEQ; step++) {
        const int rp = step & 1;
        const float4* hsrc = reinterpret_cast<const float4*>(
            g_hst + (size_t)rp * HPAR);
        u32* hdst = g_hst + (size_t)(rp ^ 1) * HPAR;

        // prefetch this step's xproj slice
        float2 xp[2][2];
#pragma unroll
        for (int nt = 0; nt < 2; nt++) {
            int c0i = nh * 16 + nt * 8 + 2 * t;
            int gc = (c0i >> 3) * HDIM + jt + (c0i & 7);
            int b0 = mt * 16 + g;
            xp[nt][0] = *reinterpret_cast<const float2*>(
                g_xproj + ((size_t)b0 * SEQ + step) * GDIM + gc);
            xp[nt][1] = *reinterpret_cast<const float2*>(
                g_xproj + ((size_t)(b0 + 8) * SEQ + step) * GDIM + gc);
        }

        stage(hsrc, 0, 0);
        CPA_COMMIT();

        float acc[2][4];
#pragma unroll
        for (int nt = 0; nt < 2; nt++)
#pragma unroll
            for (int e = 0; e < 4; e++) acc[nt][e] = 0.f;

        for (int ck = 0; ck < 8; ck++) {
            if (ck < 7) { stage(hsrc, ck + 1, (ck + 1) & 1); CPA_COMMIT(); CPA_WAIT1(); }
            else CPA_WAIT0();
            __syncthreads();

            const u32* B0 = smu + (ck & 1) * SBUF;
            int ar = mt * 16 + g;
#pragma unroll
            for (int ks = 0; ks < 8; ks++) {
                int ko = ks * 8 + 2 * t;
                uint2 axh = *reinterpret_cast<const uint2*>(&B0[ar * 72 + ko]);
                uint2 ayh = *reinterpret_cast<const uint2*>(&B0[(ar + 8) * 72 + ko]);
                uint2 axl = *reinterpret_cast<const uint2*>(&B0[4608 + ar * 72 + ko]);
                uint2 ayl = *reinterpret_cast<const uint2*>(&B0[4608 + (ar + 8) * 72 + ko]);
#pragma unroll
                for (int nt = 0; nt < 2; nt++) {
                    int nr = nh * 16 + nt * 8 + g;
                    uint2 bh = *reinterpret_cast<const uint2*>(&B0[9216 + nr * 72 + ko]);
                    uint2 bl = *reinterpret_cast<const uint2*>(&B0[11520 + nr * 72 + ko]);
                    float* d = acc[nt];
                    mma16(d, axh.x, ayh.x, axh.y, ayh.y, bh.x, bh.y);
                    mma16(d, axl.x, ayl.x, axl.y, ayl.y, bh.x, bh.y);
                    mma16(d, axh.x, ayh.x, axh.y, ayh.y, bl.x, bl.y);
                }
            }
            __syncthreads();
        }

        // gate exchange (overlays buf0; 64x33 floats)
        float* gsm = reinterpret_cast<float*>(smu);
#pragma unroll
        for (int nt = 0; nt < 2; nt++) {
            int c0i = nh * 16 + nt * 8 + 2 * t;
            int b0 = mt * 16 + g;
            gsm[b0 * 33 + c0i]           = acc[nt][0] + xp[nt][0].x;
            gsm[b0 * 33 + c0i + 1]       = acc[nt][1] + xp[nt][0].y;
            gsm[(b0 + 8) * 33 + c0i]     = acc[nt][2] + xp[nt][1].x;
            gsm[(b0 + 8) * 33 + c0i + 1] = acc[nt][3] + xp[nt][1].y;
        }
        __syncthreads();

        // pointwise update + write next-step h stage (bf16 hi/lo planes)
#pragma unroll
        for (int l = 0; l < 2; l++) {
            int pid = tid + l * 256;
            int b = pid >> 3, jj = pid & 7, j = jt + jj;
            float ig = gsm[b * 33 + jj];
            float fg = gsm[b * 33 + 8 + jj];
            float gg = gsm[b * 33 + 16 + jj];
            float og = gsm[b * 33 + 24 + jj];
            float cn = sigmoidf_(fg) * creg[l] + sigmoidf_(ig) * tanhf(gg);
            float h = sigmoidf_(og) * tanhf(cn);
            creg[l] = cn;
            out[(size_t)b * SEQ * HDIM + (size_t)step * HDIM + j] = h;

            __nv_bfloat16 hb = __float2bfloat16(h);
            float rl = h - __bfloat162float(hb);
            __nv_bfloat16 lb = __float2bfloat16(rl);
            int ck = j >> 7, pq = permq((j & 127) >> 1);
            u32* blk = hdst + (size_t)ck * HB_U32;
            unsigned short* hp = reinterpret_cast<unsigned short*>(blk + b * 72 + pq);
            unsigned short* lp = reinterpret_cast<unsigned short*>(blk + 64 * 72 + b * 72 + pq);
            hp[j & 1] = __bfloat16_as_ushort(hb);
            lp[j & 1] = __bfloat16_as_ushort(lb);

            if (write_tail && step == SEQ - 1) {
                float* tail = out + (size_t)SEQ * BATCH * HDIM;
                tail[b * HDIM + j] = h;
                tail[BATCH * HDIM + b * HDIM + j] = cn;
            }
        }

        if (step < SEQ - 1) gbar2(base_epoch + step + 1);
    }
}

// ---------------------------------------------------------------------------
// Launch
// ---------------------------------------------------------------------------
extern "C" void kernel_launch(void* const* d_in, const int* in_sizes, int n_in,
                              void* d_out, int out_size) {
    const float* inp  = (const float*)d_in[0];
    const float* h0   = (const float*)d_in[1];
    const float* c0   = (const float*)d_in[2];
    const float* W_ih = (const float*)d_in[3];
    const float* W_hh = (const float*)d_in[4];
    const float* b_ih = (const float*)d_in[5];
    const float* b_hh = (const float*)d_in[6];
    float* out = (float*)d_out;

    cudaFuncSetAttribute(xproj_tc_kernel,
                         cudaFuncAttributeMaxDynamicSharedMemorySize, XSMEM);
    cudaFuncSetAttribute(lstm_persistent,
                         cudaFuncAttributeMaxDynamicSharedMemorySize, SSMEM);

    split_a_kernel<<<SEQ * BATCH * INDIM / 512, 256>>>(inp);
    split_wih_kernel<<<GDIM * INDIM / 512, 256>>>(W_ih);
    split_whh_kernel<<<GDIM * HDIM / 512, 256>>>(W_hh);
    init_state_kernel<<<BATCH * HDIM / 512, 256>>>(h0);

    dim3 gx(GDIM / 64, (SEQ * BATCH) / 128);
    xproj_tc_kernel<<<gx, 256, XSMEM>>>(b_ih, b_hh);

    int tail = (out_size >= SEQ * BATCH * HDIM + 2 * BATCH * HDIM) ? 1 : 0;
    lstm_persistent<<<128, 256, SSMEM>>>(out, c0, tail);
}

// round 12
// speedup vs baseline: 1.1943x; 1.1201x over previous
#include <cuda_runtime.h>
#include <cuda_bf16.h>
#include <math.h>
#include <string.h>

#define SEQ   512
#define BATCH 64
#define INDIM 1024
#define HDIM  1024
#define GDIM  4096   // 4*H

typedef unsigned int u32;
typedef unsigned long long u64;

// ---------------------------------------------------------------------------
// Gmem scratch (staged operands: packed bf16 hi/lo planes, u32 granules =
// bf16x2 for k-pair (2q,2q+1), permuted so fragments load as LDS.64)
// ---------------------------------------------------------------------------
__device__ float g_xproj[(size_t)SEQ * BATCH * GDIM];              // 512 MB

// A (inp) for xproj: per (mtile 0..255, ck 0..15 of K64): [hi 128x40][lo 128x40]
#define AB_U32 (2 * 128 * 40)            // 10240 u32
__device__ u32 g_ast[(size_t)256 * 16 * AB_U32];                   // 168 MB

// W_ih: per (ntile 0..63, ck 0..15): [hi 64x40][lo 64x40]
#define WI_U32 (2 * 64 * 40)             // 5120 u32
__device__ u32 g_wih2[(size_t)64 * 16 * WI_U32];                   // 21 MB

// W_hh: per (ct 0..127, ck 0..7 of K128): [hi 32x72][lo 32x72]
#define WH_U32 (2 * 32 * 72)             // 4608 u32
__device__ u32 g_whh2[(size_t)128 * 8 * WH_U32];                   // 19 MB

// h (parity double buffer): per (par, ck 0..7): [hi 64x72][lo 64x72]
#define HB_U32 (2 * 64 * 72)             // 9216 u32
#define HPAR   (8 * HB_U32)
__device__ u32 g_hst[2 * HPAR];

// Grid barrier flags (monotonic across graph replays; never reset)
__device__ u32 g_flags[128];

// ---------------------------------------------------------------------------
// Helpers
// ---------------------------------------------------------------------------
__device__ __forceinline__ void bf16_split2(float v0, float v1, u32& hi, u32& lo) {
    __nv_bfloat162 h2 = __floats2bfloat162_rn(v0, v1);
    float r0 = v0 - __low2float(h2);
    float r1 = v1 - __high2float(h2);
    __nv_bfloat162 l2 = __floats2bfloat162_rn(r0, r1);
    memcpy(&hi, &h2, 4);
    memcpy(&lo, &l2, 4);
}

__device__ __forceinline__ void mma16(float* d, u32 a0, u32 a1, u32 a2, u32 a3,
                                      u32 b0, u32 b1) {
    asm volatile(
        "mma.sync.aligned.m16n8k16.row.col.f32.bf16.bf16.f32 "
        "{%0,%1,%2,%3}, {%4,%5,%6,%7}, {%8,%9}, {%0,%1,%2,%3};"
        : "+f"(d[0]), "+f"(d[1]), "+f"(d[2]), "+f"(d[3])
        : "r"(a0), "r"(a1), "r"(a2), "r"(a3), "r"(b0), "r"(b1));
}

// granule permutation within each 8-granule (16-k) group: pairs (q, q+4) adjacent
__device__ __forceinline__ int permq(int q) {
    return (q & ~7) | ((q & 3) << 1) | ((q >> 2) & 1);
}

__device__ __forceinline__ float sigmoidf_(float x) {
    return 1.f / (1.f + expf(-x));
}

__device__ __forceinline__ u32 smem_u32(const void* p) {
    u32 a;
    asm("{ .reg .u64 t; cvta.to.shared.u64 t, %1; cvt.u32.u64 %0, t; }"
        : "=r"(a) : "l"(p));
    return a;
}

__device__ __forceinline__ void cpa16(u32 dst, const float4* src) {
    asm volatile("cp.async.cg.shared.global [%0], [%1], 16;"
                 :: "r"(dst), "l"(src));
}
#define CPA_COMMIT() asm volatile("cp.async.commit_group;" ::: "memory")
#define CPA_WAIT1()  asm volatile("cp.async.wait_group 1;" ::: "memory")
#define CPA_WAIT0()  asm volatile("cp.async.wait_group 0;" ::: "memory")

// Grid-wide barrier: per-CTA release flags + warp0 polls all 128.
// st.release after __syncthreads publishes all CTA writes (no membar.gpu).
__device__ __forceinline__ void gbar2(u32 target) {
    __syncthreads();
    if (threadIdx.x < 32) {
        if (threadIdx.x == 0) {
            asm volatile("st.release.gpu.global.u32 [%0], %1;"
                         :: "l"(&g_flags[blockIdx.x]), "r"(target) : "memory");
        }
        const u32* f = &g_flags[threadIdx.x * 4];
        for (;;) {
            u32 v0, v1, v2, v3;
            asm volatile("ld.acquire.gpu.global.u32 %0, [%1];" : "=r"(v0) : "l"(f + 0) : "memory");
            asm volatile("ld.acquire.gpu.global.u32 %0, [%1];" : "=r"(v1) : "l"(f + 1) : "memory");
            asm volatile("ld.acquire.gpu.global.u32 %0, [%1];" : "=r"(v2) : "l"(f + 2) : "memory");
            asm volatile("ld.acquire.gpu.global.u32 %0, [%1];" : "=r"(v3) : "l"(f + 3) : "memory");
            bool ok = (v0 >= target) && (v1 >= target) && (v2 >= target) && (v3 >= target);
            if (__ballot_sync(0xffffffffu, ok) == 0xffffffffu) break;
            __nanosleep(32);
        }
    }
    __syncthreads();
}

// ---------------------------------------------------------------------------
// Prep kernels (merged so lstm_persistent is the 4th launch -> ncu captures it)
// ---------------------------------------------------------------------------
__global__ void split_a_kernel(const float* __restrict__ A) {
    int gid = blockIdx.x * 256 + threadIdx.x;        // 16.78M granules
    int m = gid >> 9, qg = gid & 511;
    float2 v = *reinterpret_cast<const float2*>(A + (size_t)m * INDIM + qg * 2);
    u32 hi, lo;
    bf16_split2(v.x, v.y, hi, lo);
    int ck = qg >> 5, pq = permq(qg & 31);
    u32* dst = g_ast + (size_t)((m >> 7) * 16 + ck) * AB_U32 + (m & 127) * 40 + pq;
    dst[0] = hi;
    dst[128 * 40] = lo;
}

__global__ void prep_misc_kernel(const float* __restrict__ W_ih,
                                 const float* __restrict__ W_hh,
                                 const float* __restrict__ h0) {
    int gid = blockIdx.x * 256 + threadIdx.x;
    if (gid < 2097152) {
        // W_ih: 4096 rows x 512 granules
        int n = gid >> 9, qg = gid & 511;
        float2 v = *reinterpret_cast<const float2*>(W_ih + (size_t)n * INDIM + qg * 2);
        u32 hi, lo;
        bf16_split2(v.x, v.y, hi, lo);
        int ck = qg >> 5, pq = permq(qg & 31);
        u32* dst = g_wih2 + (size_t)((n >> 6) * 16 + ck) * WI_U32 + (n & 63) * 40 + pq;
        dst[0] = hi;
        dst[64 * 40] = lo;
    } else if (gid < 4194304) {
        int g2 = gid - 2097152;
        int n = g2 >> 9, qg = g2 & 511;              // n = gate row 0..4095
        float2 v = *reinterpret_cast<const float2*>(W_hh + (size_t)n * HDIM + qg * 2);
        u32 hi, lo;
        bf16_split2(v.x, v.y, hi, lo);
        int gg = n >> 10, j = n & 1023;
        int ct = j >> 3, r = gg * 8 + (j & 7);
        int ck = qg >> 6, pq = permq(qg & 63);
        u32* dst = g_whh2 + (size_t)(ct * 8 + ck) * WH_U32 + r * 72 + pq;
        dst[0] = hi;
        dst[32 * 72] = lo;
    } else if (gid < 4227072) {
        int g2 = gid - 4194304;                      // 32768 granules
        int b = g2 >> 9, qg = g2 & 511;
        float2 v = *reinterpret_cast<const float2*>(h0 + (size_t)b * HDIM + qg * 2);
        u32 hi, lo;
        bf16_split2(v.x, v.y, hi, lo);
        int ck = qg >> 6, pq = permq(qg & 63);
        u32* dst = g_hst + (size_t)ck * HB_U32 + b * 72 + pq;
        dst[0] = hi;
        dst[64 * 72] = lo;
    }
}

// ---------------------------------------------------------------------------
// Kernel: x_proj = A @ W_ih^T + bias  [bf16x3 HMMA]  (unchanged from R11)
// ---------------------------------------------------------------------------
#define XBUF 15360
#define XSMEM (2 * XBUF * 4)             // 122880 B

__global__ __launch_bounds__(256) void xproj_tc_kernel(
    const float* __restrict__ b1, const float* __restrict__ b2)
{
    extern __shared__ u32 smu[];
    const u32 sbase = smem_u32(smu);
    const int tid = threadIdx.x;
    const int w = tid >> 5, lane = tid & 31;
    const int g = lane >> 2, t = lane & 3;
    const int rm = w >> 1, rn = w & 1;
    const int ntile = blockIdx.x, mtile = blockIdx.y;

    const float4* asrc = reinterpret_cast<const float4*>(
        g_ast + (size_t)(mtile * 16) * AB_U32);
    const float4* wsrc = reinterpret_cast<const float4*>(
        g_wih2 + (size_t)(ntile * 16) * WI_U32);

    auto stage = [&](int ck, int buf) {
        u32 d = sbase + (u32)buf * (XBUF * 4);
        const float4* a = asrc + (size_t)ck * (AB_U32 / 4);
        const float4* ww = wsrc + (size_t)ck * (WI_U32 / 4);
        for (int i = tid; i < AB_U32 / 4; i += 256) cpa16(d + i * 16, a + i);
        for (int i = tid; i < WI_U32 / 4; i += 256)
            cpa16(d + AB_U32 * 4 + i * 16, ww + i);
    };

    float acc[2][4][4];
#pragma unroll
    for (int mt = 0; mt < 2; mt++)
#pragma unroll
        for (int nt = 0; nt < 4; nt++)
#pragma unroll
            for (int e = 0; e < 4; e++) acc[mt][nt][e] = 0.f;

    stage(0, 0);
    CPA_COMMIT();

    for (int ck = 0; ck < 16; ck++) {
        if (ck < 15) { stage(ck + 1, (ck + 1) & 1); CPA_COMMIT(); CPA_WAIT1(); }
        else CPA_WAIT0();
        __syncthreads();

        const u32* B0 = smu + (ck & 1) * XBUF;

#pragma unroll
        for (int ks = 0; ks < 4; ks++) {
            int ko = ks * 8 + 2 * t;
            uint2 axh[2], ayh[2], axl[2], ayl[2];
#pragma unroll
            for (int mt = 0; mt < 2; mt++) {
                int ar = rm * 32 + mt * 16 + g;
                axh[mt] = *reinterpret_cast<const uint2*>(&B0[ar * 40 + ko]);
                ayh[mt] = *reinterpret_cast<const uint2*>(&B0[(ar + 8) * 40 + ko]);
                axl[mt] = *reinterpret_cast<const uint2*>(&B0[5120 + ar * 40 + ko]);
                ayl[mt] = *reinterpret_cast<const uint2*>(&B0[5120 + (ar + 8) * 40 + ko]);
            }
#pragma unroll
            for (int nt = 0; nt < 4; nt++) {
                int nr = rn * 32 + nt * 8 + g;
                uint2 bh = *reinterpret_cast<const uint2*>(&B0[10240 + nr * 40 + ko]);
                uint2 bl = *reinterpret_cast<const uint2*>(&B0[12800 + nr * 40 + ko]);
#pragma unroll
                for (int mt = 0; mt < 2; mt++) {
                    float* d = acc[mt][nt];
                    mma16(d, axh[mt].x, ayh[mt].x, axh[mt].y, ayh[mt].y, bh.x, bh.y);
                    mma16(d, axl[mt].x, ayl[mt].x, axl[mt].y, ayl[mt].y, bh.x, bh.y);
                    mma16(d, axh[mt].x, ayh[mt].x, axh[mt].y, ayh[mt].y, bl.x, bl.y);
                }
            }
        }
        __syncthreads();
    }

    const int m0 = mtile * 128, n0 = ntile * 64;
#pragma unroll
    for (int mt = 0; mt < 2; mt++) {
        int row = m0 + rm * 32 + mt * 16 + g;
#pragma unroll
        for (int nt = 0; nt < 4; nt++) {
            int col = n0 + rn * 32 + nt * 8 + 2 * t;
            float bv0 = b1[col] + b2[col];
            float bv1 = b1[col + 1] + b2[col + 1];
            float2 v0 = make_float2(acc[mt][nt][0] + bv0, acc[mt][nt][1] + bv1);
            float2 v1 = make_float2(acc[mt][nt][2] + bv0, acc[mt][nt][3] + bv1);
            *reinterpret_cast<float2*>(g_xproj + (size_t)row * GDIM + col) = v0;
            *reinterpret_cast<float2*>(g_xproj + (size_t)(row + 8) * GDIM + col) = v1;
        }
    }
}

// ---------------------------------------------------------------------------
// Persistent LSTM recurrence [bf16x3 HMMA], W_hh RESIDENT in smem.
// 128 CTAs x 256 threads. CTA ct: 8 hidden cols -> 32 gate cols.
// smem (u32): h buf0 0..9216, h buf1 9216..18432, W 18432..55296 (8 chunks).
// Total 221184 B.
// ---------------------------------------------------------------------------
#define HOFF0 0
#define WOFF  (2 * HB_U32)               // 18432 u32
#define SSMEM ((WOFF + 8 * WH_U32) * 4)  // 221184 B

__global__ __launch_bounds__(256) void lstm_persistent(
    float* __restrict__ out, const float* __restrict__ c0, int write_tail)
{
    extern __shared__ u32 smu[];
    const u32 sbase = smem_u32(smu);
    const int tid = threadIdx.x;
    const int w = tid >> 5, lane = tid & 31;
    const int g = lane >> 2, t = lane & 3;
    const int mt = w & 3, nh = w >> 2;
    const int ct = blockIdx.x, jt = ct * 8;

    // One-time W_hh load into persistent smem (147 KB)
    {
        const float4* ws = reinterpret_cast<const float4*>(
            g_whh2 + (size_t)(ct * 8) * WH_U32);
        u32 d = sbase + WOFF * 4;
        for (int i = tid; i < 8 * WH_U32 / 4; i += 256) cpa16(d + i * 16, ws + i);
        CPA_COMMIT();
    }

    // cell state in registers
    float creg[2];
#pragma unroll
    for (int l = 0; l < 2; l++) {
        int pid = tid + l * 256;
        creg[l] = c0[(pid >> 3) * HDIM + jt + (pid & 7)];
    }

    __shared__ u32 s_base;
    if (tid == 0) {
        u32 b;
        asm volatile("ld.acquire.gpu.global.u32 %0, [%1];"
                     : "=r"(b) : "l"(&g_flags[blockIdx.x]) : "memory");
        s_base = b;
    }
    __syncthreads();
    const u32 base_epoch = s_base;

    auto stage_h = [&](const float4* hsrc, int ck, int buf) {
        u32 d = sbase + (u32)buf * (HB_U32 * 4);
        const float4* h = hsrc + (size_t)ck * (HB_U32 / 4);
        for (int i = tid; i < HB_U32 / 4; i += 256) cpa16(d + i * 16, h + i);
    };

    for (int step = 0; step < SEQ; step++) {
        const int rp = step & 1;
        const float4* hsrc = reinterpret_cast<const float4*>(
            g_hst + (size_t)rp * HPAR);
        u32* hdst = g_hst + (size_t)(rp ^ 1) * HPAR;

        // prefetch this step's xproj slice (latency hidden under staging/mma)
        float2 xp[2][2];
#pragma unroll
        for (int nt = 0; nt < 2; nt++) {
            int c0i = nh * 16 + nt * 8 + 2 * t;
            int gc = (c0i >> 3) * HDIM + jt + (c0i & 7);
            int b0 = mt * 16 + g;
            xp[nt][0] = *reinterpret_cast<const float2*>(
                g_xproj + ((size_t)b0 * SEQ + step) * GDIM + gc);
            xp[nt][1] = *reinterpret_cast<const float2*>(
                g_xproj + ((size_t)(b0 + 8) * SEQ + step) * GDIM + gc);
        }

        stage_h(hsrc, 0, 0);
        CPA_COMMIT();

        float acc[2][4];
#pragma unroll
        for (int nt = 0; nt < 2; nt++)
#pragma unroll
            for (int e = 0; e < 4; e++) acc[nt][e] = 0.f;

        for (int ck = 0; ck < 8; ck++) {
            if (ck < 7) { stage_h(hsrc, ck + 1, (ck + 1) & 1); CPA_COMMIT(); CPA_WAIT1(); }
            else CPA_WAIT0();
            __syncthreads();

            const u32* H0 = smu + (ck & 1) * HB_U32;
            const u32* W0 = smu + WOFF + ck * WH_U32;
            int ar = mt * 16 + g;
#pragma unroll
            for (int ks = 0; ks < 8; ks++) {
                int ko = ks * 8 + 2 * t;
                uint2 axh = *reinterpret_cast<const uint2*>(&H0[ar * 72 + ko]);
                uint2 ayh = *reinterpret_cast<const uint2*>(&H0[(ar + 8) * 72 + ko]);
                uint2 axl = *reinterpret_cast<const uint2*>(&H0[4608 + ar * 72 + ko]);
                uint2 ayl = *reinterpret_cast<const uint2*>(&H0[4608 + (ar + 8) * 72 + ko]);
#pragma unroll
                for (int nt = 0; nt < 2; nt++) {
                    int nr = nh * 16 + nt * 8 + g;
                    uint2 bh = *reinterpret_cast<const uint2*>(&W0[nr * 72 + ko]);
                    uint2 bl = *reinterpret_cast<const uint2*>(&W0[2304 + nr * 72 + ko]);
                    float* d = acc[nt];
                    mma16(d, axh.x, ayh.x, axh.y, ayh.y, bh.x, bh.y);
                    mma16(d, axl.x, ayl.x, axl.y, ayl.y, bh.x, bh.y);
                    mma16(d, axh.x, ayh.x, axh.y, ayh.y, bl.x, bl.y);
                }
            }
            __syncthreads();
        }

        // gate exchange (overlays h buf0; 64x33 floats)
        float* gsm = reinterpret_cast<float*>(smu);
#pragma unroll
        for (int nt = 0; nt < 2; nt++) {
            int c0i = nh * 16 + nt * 8 + 2 * t;
            int b0 = mt * 16 + g;
            gsm[b0 * 33 + c0i]           = acc[nt][0] + xp[nt][0].x;
            gsm[b0 * 33 + c0i + 1]       = acc[nt][1] + xp[nt][0].y;
            gsm[(b0 + 8) * 33 + c0i]     = acc[nt][2] + xp[nt][1].x;
            gsm[(b0 + 8) * 33 + c0i + 1] = acc[nt][3] + xp[nt][1].y;
        }
        __syncthreads();

        // pointwise update + write next-step h stage (bf16 hi/lo planes)
#pragma unroll
        for (int l = 0; l < 2; l++) {
            int pid = tid + l * 256;
            int b = pid >> 3, jj = pid & 7, j = jt + jj;
            float ig = gsm[b * 33 + jj];
            float fg = gsm[b * 33 + 8 + jj];
            float gg = gsm[b * 33 + 16 + jj];
            float og = gsm[b * 33 + 24 + jj];
            float cn = sigmoidf_(fg) * creg[l] + sigmoidf_(ig) * tanhf(gg);
            float h = sigmoidf_(og) * tanhf(cn);
            creg[l] = cn;
            out[(size_t)b * SEQ * HDIM + (size_t)step * HDIM + j] = h;

            __nv_bfloat16 hb = __float2bfloat16(h);
            float rl = h - __bfloat162float(hb);
            __nv_bfloat16 lb = __float2bfloat16(rl);
            int ck = j >> 7, pq = permq((j & 127) >> 1);
            u32* blk = hdst + (size_t)ck * HB_U32;
            unsigned short* hp = reinterpret_cast<unsigned short*>(blk + b * 72 + pq);
            unsigned short* lp = reinterpret_cast<unsigned short*>(blk + 64 * 72 + b * 72 + pq);
            hp[j & 1] = __bfloat16_as_ushort(hb);
            lp[j & 1] = __bfloat16_as_ushort(lb);

            if (write_tail && step == SEQ - 1) {
                float* tail = out + (size_t)SEQ * BATCH * HDIM;
                tail[b * HDIM + j] = h;
                tail[BATCH * HDIM + b * HDIM + j] = cn;
            }
        }

        if (step < SEQ - 1) gbar2(base_epoch + step + 1);
    }
}

// ---------------------------------------------------------------------------
// Launch: split_a(1), prep_misc(2), xproj(3), lstm_persistent(4=ncu slot)
// ---------------------------------------------------------------------------
extern "C" void kernel_launch(void* const* d_in, const int* in_sizes, int n_in,
                              void* d_out, int out_size) {
    const float* inp  = (const float*)d_in[0];
    const float* h0   = (const float*)d_in[1];
    const float* c0   = (const float*)d_in[2];
    const float* W_ih = (const float*)d_in[3];
    const float* W_hh = (const float*)d_in[4];
    const float* b_ih = (const float*)d_in[5];
    const float* b_hh = (const float*)d_in[6];
    float* out = (float*)d_out;

    cudaFuncSetAttribute(xproj_tc_kernel,
                         cudaFuncAttributeMaxDynamicSharedMemorySize, XSMEM);
    cudaFuncSetAttribute(lstm_persistent,
                         cudaFuncAttributeMaxDynamicSharedMemorySize, SSMEM);

    split_a_kernel<<<SEQ * BATCH * INDIM / 512, 256>>>(inp);
    prep_misc_kernel<<<16512, 256>>>(W_ih, W_hh, h0);

    dim3 gx(GDIM / 64, (SEQ * BATCH) / 128);
    xproj_tc_kernel<<<gx, 256, XSMEM>>>(b_ih, b_hh);

    int tail = (out_size >= SEQ * BATCH * HDIM + 2 * BATCH * HDIM) ? 1 : 0;
    lstm_persistent<<<128, 256, SSMEM>>>(out, c0, tail);
}